// round 1
// baseline (speedup 1.0000x reference)
#include <cuda_runtime.h>
#include <math.h>

// ---------------- problem constants ----------------
#define S_LEN 2048
#define BATCH 2
#define NTOK  (S_LEN*BATCH)     // 4096
#define NH    16
#define DIM   2048
#define NOPE  128
#define ROPE  64
#define RHALF 32                // ROPE/2
#define VDIM  128
#define KVR   512
#define QD    (NOPE+ROPE)       // 192
#define QOUT  (NH*QD)           // 3072
#define KVOUT (KVR+ROPE)        // 576
#define DEFF  576               // effective attention dim (512 latent + 64 rope)

// ---------------- scratch (static device globals; no allocs) ----------------
__device__ float g_q   [(size_t)NTOK*QOUT];                 // x @ wq^T
__device__ float g_kv  [(size_t)NTOK*KVOUT];                // x @ wkv_a^T
__device__ float g_keff[(size_t)NTOK*DEFF];                 // [B*S, 576] = rmsnorm(c) | rope(k_pe)
__device__ float g_qeff[(size_t)BATCH*NH*S_LEN*DEFF];       // [B,H,S,576] = q_abs | rope(q_pe)
__device__ float g_scores[(size_t)BATCH*NH*S_LEN*S_LEN];    // [B,H,S,S] scores -> probs (in place)
__device__ float g_olat[(size_t)BATCH*NH*S_LEN*KVR];        // [B,H,S,512]
__device__ float g_o   [(size_t)NTOK*(NH*VDIM)];            // [B*S, 2048]
__device__ float g_cos [S_LEN*RHALF];
__device__ float g_sin [S_LEN*RHALF];

// ---------------- reduction helpers ----------------
__device__ __forceinline__ float warpMax(float v){
    #pragma unroll
    for (int o=16;o;o>>=1) v = fmaxf(v, __shfl_xor_sync(0xffffffffu, v, o));
    return v;
}
__device__ __forceinline__ float warpSum(float v){
    #pragma unroll
    for (int o=16;o;o>>=1) v += __shfl_xor_sync(0xffffffffu, v, o);
    return v;
}

// ---------------- prep kernels ----------------
__global__ void rope_prep_kernel(const float* __restrict__ ang){
    int i = blockIdx.x*blockDim.x + threadIdx.x;
    if (i < S_LEN*RHALF){
        float a = ang[i];
        g_cos[i] = cosf(a);
        g_sin[i] = sinf(a);
    }
}

// one block (128 thr) per token: rmsnorm(kv_c)*w -> keff[0:512]; rope(k_pe) -> keff[512:576]
__global__ void prep_keff_kernel(const float* __restrict__ kvw){
    int t = blockIdx.x;
    int s = t % S_LEN;
    int tid = threadIdx.x;
    const float4* kvrow = (const float4*)(g_kv + (size_t)t*KVOUT);
    float4 v = kvrow[tid];                       // 128 threads * 4 = 512
    float ss = v.x*v.x + v.y*v.y + v.z*v.z + v.w*v.w;
    ss = warpSum(ss);
    __shared__ float red[4];
    if ((tid&31)==0) red[tid>>5] = ss;
    __syncthreads();
    float tot = red[0]+red[1]+red[2]+red[3];
    float r = rsqrtf(tot*(1.0f/KVR) + 1e-6f);
    float4 w = ((const float4*)kvw)[tid];
    float4 o;
    o.x = v.x*r*w.x; o.y = v.y*r*w.y; o.z = v.z*r*w.z; o.w = v.w*r*w.w;
    ((float4*)(g_keff + (size_t)t*DEFF))[tid] = o;
    if (tid < RHALF){
        const float* pe = g_kv + (size_t)t*KVOUT + KVR;
        float xr = pe[2*tid], xi = pe[2*tid+1];
        float c  = g_cos[s*RHALF+tid], sn = g_sin[s*RHALF+tid];
        float* dst = g_keff + (size_t)t*DEFF + KVR;
        dst[2*tid]   = xr*c - xi*sn;
        dst[2*tid+1] = xr*sn + xi*c;
    }
}

// rope q_pe -> qeff[..., 512:576]; grid (NTOK, NH), 32 threads
__global__ void prep_qpe_kernel(){
    int t = blockIdx.x, h = blockIdx.y;
    int b = t / S_LEN, s = t % S_LEN;
    int i = threadIdx.x;   // 0..31
    const float* src = g_q + (size_t)t*QOUT + h*QD + NOPE;
    float* dst = g_qeff + ((size_t)(b*NH+h)*S_LEN + s)*DEFF + KVR;
    float xr = src[2*i], xi = src[2*i+1];
    float c  = g_cos[s*RHALF+i], sn = g_sin[s*RHALF+i];
    dst[2*i]   = xr*c - xi*sn;
    dst[2*i+1] = xr*sn + xi*c;
}

// ---------------- generic batched SGEMM ----------------
// C[M,N] = alpha * A[M,K] @ op(B);  op(B)=B^T with B[N,K] if TRANSB else B[K,N].
// All of M,N multiples of 64; K (and klimit bound) multiples of 16.
// z batching: off = (z%zdiv)*s?l + (z/zdiv)*s?h  (elements).
// causal: skip blocks with bx > by (BM==BN).  klimit: K-loop capped at (by+1)*BM.
#define BM 64
#define BN 64
#define BK 16

template<bool TRANSB>
__global__ __launch_bounds__(256) void sgemm_kernel(
    const float* __restrict__ Ag, const float* __restrict__ Bg, float* __restrict__ Cg,
    int M, int N, int K, int lda, int ldb, int ldc, int zdiv,
    long long sAl, long long sAh, long long sBl, long long sBh,
    long long sCl, long long sCh,
    float alpha, int causal, int klimit)
{
    if (causal && blockIdx.x > blockIdx.y) return;
    const int bz = blockIdx.z;
    const int zl = bz % zdiv, zh = bz / zdiv;
    const float* A = Ag + zl*sAl + zh*sAh;
    const float* B = Bg + zl*sBl + zh*sBh;
    float* C = Cg + zl*sCl + zh*sCh;

    int kEnd = K;
    if (klimit){
        int kl = (int)(blockIdx.y + 1) * BM;
        if (kl < kEnd) kEnd = kl;
    }

    __shared__ float As[BK][BM];
    __shared__ float Bs[BK][BN];

    const int tid = threadIdx.x;
    const int tx = tid & 15, ty = tid >> 4;
    const int m0 = blockIdx.y*BM, n0 = blockIdx.x*BN;

    const int aRow = tid >> 2, aK = (tid & 3) << 2;      // A: 64 rows x 16 k
    float acc[4][4] = {};

    const float* Aptr = A + (long long)(m0 + aRow)*lda + aK;
    const float* Bptr;
    if (TRANSB) Bptr = B + (long long)(n0 + (tid>>2))*ldb + ((tid&3)<<2);
    else        Bptr = B + (long long)(tid>>4)*ldb + n0 + ((tid&15)<<2);

    for (int k0 = 0; k0 < kEnd; k0 += BK){
        float4 av = *(const float4*)(Aptr + k0);
        float4 bv;
        if (TRANSB) bv = *(const float4*)(Bptr + k0);
        else        bv = *(const float4*)(Bptr + (long long)k0*ldb);

        __syncthreads();   // previous tile fully consumed
        As[aK+0][aRow] = av.x; As[aK+1][aRow] = av.y;
        As[aK+2][aRow] = av.z; As[aK+3][aRow] = av.w;
        if (TRANSB){
            const int bRow = tid>>2, bK = (tid&3)<<2;
            Bs[bK+0][bRow] = bv.x; Bs[bK+1][bRow] = bv.y;
            Bs[bK+2][bRow] = bv.z; Bs[bK+3][bRow] = bv.w;
        } else {
            *(float4*)&Bs[tid>>4][(tid&15)<<2] = bv;
        }
        __syncthreads();

        #pragma unroll
        for (int k=0;k<BK;k++){
            float4 a = *(const float4*)&As[k][ty<<2];
            float4 b = *(const float4*)&Bs[k][tx<<2];
            acc[0][0] += a.x*b.x; acc[0][1] += a.x*b.y; acc[0][2] += a.x*b.z; acc[0][3] += a.x*b.w;
            acc[1][0] += a.y*b.x; acc[1][1] += a.y*b.y; acc[1][2] += a.y*b.z; acc[1][3] += a.y*b.w;
            acc[2][0] += a.z*b.x; acc[2][1] += a.z*b.y; acc[2][2] += a.z*b.z; acc[2][3] += a.z*b.w;
            acc[3][0] += a.w*b.x; acc[3][1] += a.w*b.y; acc[3][2] += a.w*b.z; acc[3][3] += a.w*b.w;
        }
    }

    #pragma unroll
    for (int i=0;i<4;i++){
        float4 o;
        o.x = acc[i][0]*alpha; o.y = acc[i][1]*alpha;
        o.z = acc[i][2]*alpha; o.w = acc[i][3]*alpha;
        *(float4*)(C + (long long)(m0 + (ty<<2) + i)*ldc + n0 + (tx<<2)) = o;
    }
}

// ---------------- causal row softmax (in place) ----------------
// grid (S, B*H), 128 threads; reads t<=s only, zeroes (s, roundup64(s+1)).
__global__ void softmax_kernel(float* __restrict__ sc){
    const int s = blockIdx.x;
    const long long z = blockIdx.y;
    float* row = sc + (z*S_LEN + (long long)s)*S_LEN;
    const int n = s + 1;
    const int tid = threadIdx.x;

    float mx = -1e30f;
    for (int t = tid; t < n; t += 128) mx = fmaxf(mx, row[t]);
    mx = warpMax(mx);
    __shared__ float redm[4], reds[4];
    if ((tid&31)==0) redm[tid>>5] = mx;
    __syncthreads();
    mx = fmaxf(fmaxf(redm[0],redm[1]), fmaxf(redm[2],redm[3]));

    float sum = 0.f;
    for (int t = tid; t < n; t += 128){
        float e = __expf(row[t] - mx);
        row[t] = e;
        sum += e;
    }
    sum = warpSum(sum);
    if ((tid&31)==0) reds[tid>>5] = sum;
    __syncthreads();
    sum = reds[0]+reds[1]+reds[2]+reds[3];
    float inv = 1.0f / sum;
    for (int t = tid; t < n; t += 128) row[t] *= inv;

    const int nend = ((s>>6)+1)<<6;      // zero the diagonal-block tail read by PV
    for (int t = n + tid; t < nend; t += 128) row[t] = 0.f;
}

// ---------------- host side ----------------
static void launch_gemm(bool transb,
    const float* A, const float* B, float* C,
    int M, int N, int K, int lda, int ldb, int ldc,
    int Z, int zdiv,
    long long sAl, long long sAh, long long sBl, long long sBh,
    long long sCl, long long sCh,
    float alpha, bool causal, bool klimit)
{
    dim3 grid(N/BN, M/BM, Z);
    if (transb)
        sgemm_kernel<true ><<<grid, 256>>>(A,B,C,M,N,K,lda,ldb,ldc,zdiv,
            sAl,sAh,sBl,sBh,sCl,sCh,alpha,causal?1:0,klimit?1:0);
    else
        sgemm_kernel<false><<<grid, 256>>>(A,B,C,M,N,K,lda,ldb,ldc,zdiv,
            sAl,sAh,sBl,sBh,sCl,sCh,alpha,causal?1:0,klimit?1:0);
}

extern "C" void kernel_launch(void* const* d_in, const int* in_sizes, int n_in,
                              void* d_out, int out_size)
{
    (void)in_sizes; (void)n_in; (void)out_size;
    const float* x      = (const float*)d_in[0];   // (B,S,2048)
    const float* angles = (const float*)d_in[1];   // (S,32)
    const float* wq     = (const float*)d_in[2];   // (3072,2048)
    const float* wkv_a  = (const float*)d_in[3];   // (576,2048)
    const float* wkv_b  = (const float*)d_in[4];   // (4096,512)
    const float* wo     = (const float*)d_in[5];   // (2048,2048)
    const float* kvw    = (const float*)d_in[6];   // (512,)
    float* out = (float*)d_out;                    // (B,S,2048)

    float *q,*kv,*keff,*qeff,*sc,*olat,*o;
    cudaGetSymbolAddress((void**)&q,    g_q);
    cudaGetSymbolAddress((void**)&kv,   g_kv);
    cudaGetSymbolAddress((void**)&keff, g_keff);
    cudaGetSymbolAddress((void**)&qeff, g_qeff);
    cudaGetSymbolAddress((void**)&sc,   g_scores);
    cudaGetSymbolAddress((void**)&olat, g_olat);
    cudaGetSymbolAddress((void**)&o,    g_o);

    const double msc = 0.1*log(40.0) + 1.0;
    const float softmax_scale = (float)(pow((double)QD, -0.5)*msc*msc);

    // 1) rope tables
    rope_prep_kernel<<<(S_LEN*RHALF+127)/128, 128>>>(angles);

    // 2) q = x @ wq^T   (4096 x 3072, K=2048)
    launch_gemm(true, x, wq, q, NTOK, QOUT, DIM, DIM, DIM, QOUT,
                1, 1, 0,0, 0,0, 0,0, 1.f, false, false);

    // 3) kv = x @ wkv_a^T  (4096 x 576, K=2048)
    launch_gemm(true, x, wkv_a, kv, NTOK, KVOUT, DIM, DIM, DIM, KVOUT,
                1, 1, 0,0, 0,0, 0,0, 1.f, false, false);

    // 4) keff = rmsnorm(kv_c)*w | rope(k_pe)
    prep_keff_kernel<<<NTOK, 128>>>(kvw);

    // 5) qeff[...,512:576] = rope(q_pe)
    prep_qpe_kernel<<<dim3(NTOK, NH), 32>>>();

    // 6) qeff[...,0:512] = q_nope @ wkv_b_nope   (per (b,h): 2048x512, K=128)
    launch_gemm(false, q, wkv_b, qeff, S_LEN, KVR, NOPE, QOUT, KVR, DEFF,
                BATCH*NH, NH,
                (long long)QD, (long long)S_LEN*QOUT,
                (long long)(NOPE+VDIM)*KVR, 0,
                (long long)S_LEN*DEFF, (long long)NH*S_LEN*DEFF,
                1.f, false, false);

    // 7) scores = scale * qeff @ keff^T  (per (b,h): 2048x2048, K=576), causal block skip
    launch_gemm(true, qeff, keff, sc, S_LEN, S_LEN, DEFF, DEFF, DEFF, S_LEN,
                BATCH*NH, NH,
                (long long)S_LEN*DEFF, (long long)NH*S_LEN*DEFF,
                0, (long long)S_LEN*DEFF,
                (long long)S_LEN*S_LEN, (long long)NH*S_LEN*S_LEN,
                softmax_scale, true, false);

    // 8) causal softmax in place
    softmax_kernel<<<dim3(S_LEN, BATCH*NH), 128>>>(sc);

    // 9) olat = probs @ c  (per (b,h): 2048x512, K capped causally)
    launch_gemm(false, sc, keff, olat, S_LEN, KVR, S_LEN, S_LEN, DEFF, KVR,
                BATCH*NH, NH,
                (long long)S_LEN*S_LEN, (long long)NH*S_LEN*S_LEN,
                0, (long long)S_LEN*DEFF,
                (long long)S_LEN*KVR, (long long)NH*S_LEN*KVR,
                1.f, false, true);

    // 10) o[:, h*128:(h+1)*128] = olat_h @ wkv_b_v^T  (per (b,h): 2048x128, K=512)
    launch_gemm(true, olat, wkv_b + (size_t)NOPE*KVR, o, S_LEN, VDIM, KVR,
                KVR, KVR, NH*VDIM,
                BATCH*NH, NH,
                (long long)S_LEN*KVR, (long long)NH*S_LEN*KVR,
                (long long)(NOPE+VDIM)*KVR, 0,
                (long long)VDIM, (long long)S_LEN*NH*VDIM,
                1.f, false, false);

    // 11) out = o @ wo^T  (4096 x 2048, K=2048)
    launch_gemm(true, o, wo, out, NTOK, DIM, NH*VDIM, NH*VDIM, NH*VDIM, DIM,
                1, 1, 0,0, 0,0, 0,0, 1.f, false, false);
}

// round 3
// speedup vs baseline: 3.4972x; 3.4972x over previous
#include <cuda_runtime.h>
#include <math.h>
#include <stdint.h>

// ---------------- problem constants ----------------
#define S_LEN 2048
#define BATCH 2
#define NTOK  (S_LEN*BATCH)     // 4096
#define NH    16
#define DIM   2048
#define NOPE  128
#define ROPE  64
#define RHALF 32                // ROPE/2
#define VDIM  128
#define KVR   512
#define QD    (NOPE+ROPE)       // 192
#define QOUT  (NH*QD)           // 3072
#define KVOUT (KVR+ROPE)        // 576
#define DEFF  576               // effective attention dim (512 latent + 64 rope)

#define NSTAGE 3

typedef long long ll;

// ---------------- scratch (static device globals; no allocs) ----------------
__device__ float g_q   [(size_t)NTOK*QOUT];
__device__ float g_kv  [(size_t)NTOK*KVOUT];
__device__ float g_keff[(size_t)NTOK*DEFF];
__device__ float g_qeff[(size_t)BATCH*NH*S_LEN*DEFF];
__device__ float g_scores[(size_t)BATCH*NH*S_LEN*S_LEN];
__device__ float g_olat[(size_t)BATCH*NH*S_LEN*KVR];
__device__ float g_o   [(size_t)NTOK*(NH*VDIM)];
__device__ float g_cos [S_LEN*RHALF];
__device__ float g_sin [S_LEN*RHALF];

// ---------------- helpers ----------------
__device__ __forceinline__ float warpMax(float v){
    #pragma unroll
    for (int o=16;o;o>>=1) v = fmaxf(v, __shfl_xor_sync(0xffffffffu, v, o));
    return v;
}
__device__ __forceinline__ float warpSum(float v){
    #pragma unroll
    for (int o=16;o;o>>=1) v += __shfl_xor_sync(0xffffffffu, v, o);
    return v;
}
__device__ __forceinline__ uint32_t smem_u32(const void* p){
    uint32_t a;
    asm("{ .reg .u64 t; cvta.to.shared.u64 t, %1; cvt.u32.u64 %0, t; }" : "=r"(a) : "l"(p));
    return a;
}
__device__ __forceinline__ uint32_t f2tf32(float f){
    uint32_t r; asm("cvt.rna.tf32.f32 %0, %1;" : "=r"(r) : "f"(f)); return r;
}
__device__ __forceinline__ void mma_tf32_16x8x8(float* d, const uint32_t* a, const uint32_t* b){
    asm volatile(
        "mma.sync.aligned.m16n8k8.row.col.f32.tf32.tf32.f32 "
        "{%0,%1,%2,%3}, {%4,%5,%6,%7}, {%8,%9}, {%0,%1,%2,%3};"
        : "+f"(d[0]), "+f"(d[1]), "+f"(d[2]), "+f"(d[3])
        : "r"(a[0]), "r"(a[1]), "r"(a[2]), "r"(a[3]), "r"(b[0]), "r"(b[1]));
}
__device__ __forceinline__ void cp16(uint32_t dst, const float* src){
    asm volatile("cp.async.cg.shared.global [%0], [%1], 16;\n" :: "r"(dst), "l"(src) : "memory");
}
__device__ __forceinline__ void cp_commit(){ asm volatile("cp.async.commit_group;\n" ::: "memory"); }
__device__ __forceinline__ void cp_wait1(){ asm volatile("cp.async.wait_group 1;\n" ::: "memory"); }

// swizzled offset within a tile: row-major 128B rows (32 floats), 16B granule XOR (row&7)
__device__ __forceinline__ const float* swp(const char* base, int row, int g, int off){
    return (const float*)(base + row*128 + ((g ^ (row&7))<<4) + (off<<2));
}

// ---------------- prep kernels ----------------
__global__ void rope_prep_kernel(const float* __restrict__ ang){
    int i = blockIdx.x*blockDim.x + threadIdx.x;
    if (i < S_LEN*RHALF){
        float a = ang[i];
        g_cos[i] = cosf(a);
        g_sin[i] = sinf(a);
    }
}

__global__ void prep_keff_kernel(const float* __restrict__ kvw){
    int t = blockIdx.x;
    int s = t % S_LEN;
    int tid = threadIdx.x;
    const float4* kvrow = (const float4*)(g_kv + (size_t)t*KVOUT);
    float4 v = kvrow[tid];
    float ss = v.x*v.x + v.y*v.y + v.z*v.z + v.w*v.w;
    ss = warpSum(ss);
    __shared__ float red[4];
    if ((tid&31)==0) red[tid>>5] = ss;
    __syncthreads();
    float tot = red[0]+red[1]+red[2]+red[3];
    float r = rsqrtf(tot*(1.0f/KVR) + 1e-6f);
    float4 w = ((const float4*)kvw)[tid];
    float4 o;
    o.x = v.x*r*w.x; o.y = v.y*r*w.y; o.z = v.z*r*w.z; o.w = v.w*r*w.w;
    ((float4*)(g_keff + (size_t)t*DEFF))[tid] = o;
    if (tid < RHALF){
        const float* pe = g_kv + (size_t)t*KVOUT + KVR;
        float xr = pe[2*tid], xi = pe[2*tid+1];
        float c  = g_cos[s*RHALF+tid], sn = g_sin[s*RHALF+tid];
        float* dst = g_keff + (size_t)t*DEFF + KVR;
        dst[2*tid]   = xr*c - xi*sn;
        dst[2*tid+1] = xr*sn + xi*c;
    }
}

__global__ void prep_qpe_kernel(){
    int t = blockIdx.x, h = blockIdx.y;
    int b = t / S_LEN, s = t % S_LEN;
    int i = threadIdx.x;   // 0..31
    const float* src = g_q + (size_t)t*QOUT + h*QD + NOPE;
    float* dst = g_qeff + ((size_t)(b*NH+h)*S_LEN + s)*DEFF + KVR;
    float xr = src[2*i], xi = src[2*i+1];
    float c  = g_cos[s*RHALF+i], sn = g_sin[s*RHALF+i];
    dst[2*i]   = xr*c - xi*sn;
    dst[2*i+1] = xr*sn + xi*c;
}

// ---------------- tf32 mma.sync batched GEMM ----------------
// C[M,N] = alpha * A[M,K] @ op(B); TRANSB: B[N,K] (K-contig), else B[K,N].
// BM=128, BN=BN_T (128 or 64), BK=32. 256 threads, 8 warps.
template<int BN_T, bool TRANSB>
__global__ __launch_bounds__(256,2) void mma_gemm(
    const float* __restrict__ Ag, const float* __restrict__ Bg, float* __restrict__ Cg,
    int K, int lda, int ldb, int ldc, int zdiv,
    ll sAl, ll sAh, ll sBl, ll sBh, ll sCl, ll sCh,
    float alpha, int causal, int klimit)
{
    if (causal && blockIdx.x > blockIdx.y) return;
    constexpr int WN  = BN_T/32;     // warps along n
    constexpr int WM  = 8/WN;        // warps along m
    constexpr int WTM = 128/WM;      // warp tile m (64 or 32)
    constexpr int MF  = WTM/16;      // m fragments per warp
    constexpr int NF  = 4;           // 32/8 n fragments per warp
    constexpr int SA  = 128*128;     // A tile bytes (128 rows x 128B)
    constexpr int SB  = BN_T*128;    // B tile bytes
    constexpr int STG = SA + SB;

    extern __shared__ char smc[];
    const uint32_t sbase = smem_u32(smc);

    const int tid = threadIdx.x, lane = tid & 31, wid = tid >> 5;
    const int wm = wid / WN, wn = wid % WN;
    const int grp = lane >> 2, tig = lane & 3;
    const int zl = blockIdx.z % zdiv, zh = blockIdx.z / zdiv;
    const float* A = Ag + (ll)blockIdx.y*128*lda + zl*sAl + zh*sAh;
    const float* B = Bg + zl*sBl + zh*sBh;
    const ll n0 = (ll)blockIdx.x * BN_T;

    int kEnd = K;
    if (klimit){ int kl = ((int)blockIdx.y + 1)*128; if (kl < kEnd) kEnd = kl; }
    const int nk = kEnd >> 5;

    float acc[MF][NF][4];
    #pragma unroll
    for (int i=0;i<MF;i++)
        #pragma unroll
        for (int j=0;j<NF;j++)
            #pragma unroll
            for (int c=0;c<4;c++) acc[i][j][c] = 0.f;

    const int am  = tid >> 3;   // row base (+= i*32)
    const int akq = tid & 7;    // 16B granule along k

    // ---- stage loader ----
    auto LOAD = [&](int kb){
        const int s = kb % NSTAGE;
        const uint32_t As = sbase + (uint32_t)(s*STG);
        const uint32_t Bs = As + SA;
        const float* Ak = A + (kb << 5);
        #pragma unroll
        for (int i=0;i<4;i++){
            int m = am + i*32;
            cp16(As + (uint32_t)(m*128 + ((akq ^ (m&7))<<4)),
                 Ak + (ll)m*lda + (akq<<2));
        }
        if (TRANSB){
            const float* Bk = B + n0*ldb + (kb << 5);
            #pragma unroll
            for (int i=0;i<BN_T/32;i++){
                int n = am + i*32;
                cp16(Bs + (uint32_t)(n*128 + ((akq ^ (n&7))<<4)),
                     Bk + (ll)n*ldb + (akq<<2));
            }
        } else {
            const float* Bk = B + ((ll)(kb << 5))*ldb + n0;
            char* Bsc = smc + s*STG + SA;
            #pragma unroll
            for (int i=0;i<BN_T/32;i++){
                int kR = tid & 31, n4 = (tid >> 5) + i*8;
                float4 v = *(const float4*)(Bk + (ll)kR*ldb + (n4<<2));
                #pragma unroll
                for (int j=0;j<4;j++){
                    int n = n4*4 + j;
                    *(float*)(Bsc + n*128 + (((kR>>2) ^ (n&7))<<4) + ((kR&3)<<2))
                        = (&v.x)[j];
                }
            }
        }
        cp_commit();
    };

    #pragma unroll
    for (int kb=0; kb<NSTAGE-1; kb++) if (kb < nk) LOAD(kb);

    for (int k=0; k<nk; k++){
        cp_wait1();
        __syncthreads();
        if (k + NSTAGE - 1 < nk) LOAD(k + NSTAGE - 1);
        else cp_commit();

        const int s = k % NSTAGE;
        const char* As = smc + s*STG + wm*WTM*128;
        const char* Bs = smc + s*STG + SA + wn*32*128;

        #pragma unroll
        for (int kk=0; kk<4; kk++){
            uint32_t a[MF][4], b[NF][2];
            #pragma unroll
            for (int mf=0; mf<MF; mf++){
                int r0 = mf*16 + grp, r1 = r0 + 8;
                a[mf][0] = f2tf32(*swp(As, r0, 2*kk,   tig));
                a[mf][1] = f2tf32(*swp(As, r1, 2*kk,   tig));
                a[mf][2] = f2tf32(*swp(As, r0, 2*kk+1, tig));
                a[mf][3] = f2tf32(*swp(As, r1, 2*kk+1, tig));
            }
            #pragma unroll
            for (int nf=0; nf<NF; nf++){
                int c0 = nf*8 + grp;
                b[nf][0] = f2tf32(*swp(Bs, c0, 2*kk,   tig));
                b[nf][1] = f2tf32(*swp(Bs, c0, 2*kk+1, tig));
            }
            #pragma unroll
            for (int mf=0; mf<MF; mf++)
                #pragma unroll
                for (int nf=0; nf<NF; nf++)
                    mma_tf32_16x8x8(acc[mf][nf], a[mf], b[nf]);
        }
    }

    // ---- epilogue ----
    float* Cw = Cg + zl*sCl + zh*sCh
              + ((ll)blockIdx.y*128 + wm*WTM)*ldc + n0 + wn*32;
    #pragma unroll
    for (int mf=0; mf<MF; mf++){
        int r0 = mf*16 + grp;
        #pragma unroll
        for (int nf=0; nf<NF; nf++){
            int c = nf*8 + tig*2;
            float2 lo, hi;
            lo.x = acc[mf][nf][0]*alpha; lo.y = acc[mf][nf][1]*alpha;
            hi.x = acc[mf][nf][2]*alpha; hi.y = acc[mf][nf][3]*alpha;
            *(float2*)(Cw + (ll)r0*ldc + c)     = lo;
            *(float2*)(Cw + (ll)(r0+8)*ldc + c) = hi;
        }
    }
}

// ---------------- causal row softmax (in place) ----------------
__global__ void softmax_kernel(float* __restrict__ sc){
    const int s = blockIdx.x;
    const ll z = blockIdx.y;
    float* row = sc + (z*S_LEN + (ll)s)*S_LEN;
    const int n = s + 1;
    const int tid = threadIdx.x;

    float mx = -1e30f;
    for (int t = tid; t < n; t += 128) mx = fmaxf(mx, row[t]);
    mx = warpMax(mx);
    __shared__ float redm[4], reds[4];
    if ((tid&31)==0) redm[tid>>5] = mx;
    __syncthreads();
    mx = fmaxf(fmaxf(redm[0],redm[1]), fmaxf(redm[2],redm[3]));

    float sum = 0.f;
    for (int t = tid; t < n; t += 128){
        float e = __expf(row[t] - mx);
        row[t] = e;
        sum += e;
    }
    sum = warpSum(sum);
    if ((tid&31)==0) reds[tid>>5] = sum;
    __syncthreads();
    sum = reds[0]+reds[1]+reds[2]+reds[3];
    float inv = 1.0f / sum;
    for (int t = tid; t < n; t += 128) row[t] *= inv;

    const int nend = ((s>>7)+1)<<7;   // zero tail of 128-wide diagonal block (PV reads it)
    for (int t = n + tid; t < nend; t += 128) row[t] = 0.f;
}

// ---------------- host side ----------------
static void launch_mma(bool transb, int BN,
    const float* A, const float* B, float* C,
    int M, int N, int K, int lda, int ldb, int ldc,
    int Z, int zdiv,
    ll sAl, ll sAh, ll sBl, ll sBh, ll sCl, ll sCh,
    float alpha, bool causal, bool klimit)
{
    dim3 grid(N/BN, M/128, Z);
    int c = causal ? 1 : 0, kl = klimit ? 1 : 0;
    size_t sm = (size_t)NSTAGE * (128*128 + (size_t)BN*128);
    if (BN == 128){
        if (transb){
            cudaFuncSetAttribute(mma_gemm<128,true>, cudaFuncAttributeMaxDynamicSharedMemorySize, (int)sm);
            mma_gemm<128,true><<<grid,256,sm>>>(A,B,C,K,lda,ldb,ldc,zdiv,sAl,sAh,sBl,sBh,sCl,sCh,alpha,c,kl);
        } else {
            cudaFuncSetAttribute(mma_gemm<128,false>, cudaFuncAttributeMaxDynamicSharedMemorySize, (int)sm);
            mma_gemm<128,false><<<grid,256,sm>>>(A,B,C,K,lda,ldb,ldc,zdiv,sAl,sAh,sBl,sBh,sCl,sCh,alpha,c,kl);
        }
    } else {
        cudaFuncSetAttribute(mma_gemm<64,true>, cudaFuncAttributeMaxDynamicSharedMemorySize, (int)sm);
        mma_gemm<64,true><<<grid,256,sm>>>(A,B,C,K,lda,ldb,ldc,zdiv,sAl,sAh,sBl,sBh,sCl,sCh,alpha,c,kl);
    }
}

extern "C" void kernel_launch(void* const* d_in, const int* in_sizes, int n_in,
                              void* d_out, int out_size)
{
    (void)in_sizes; (void)n_in; (void)out_size;
    const float* x      = (const float*)d_in[0];   // (B,S,2048)
    const float* angles = (const float*)d_in[1];   // (S,32)
    const float* wq     = (const float*)d_in[2];   // (3072,2048)
    const float* wkv_a  = (const float*)d_in[3];   // (576,2048)
    const float* wkv_b  = (const float*)d_in[4];   // (4096,512)
    const float* wo     = (const float*)d_in[5];   // (2048,2048)
    const float* kvw    = (const float*)d_in[6];   // (512,)
    float* out = (float*)d_out;                    // (B,S,2048)

    float *q,*kv,*keff,*qeff,*sc,*olat,*o;
    cudaGetSymbolAddress((void**)&q,    g_q);
    cudaGetSymbolAddress((void**)&kv,   g_kv);
    cudaGetSymbolAddress((void**)&keff, g_keff);
    cudaGetSymbolAddress((void**)&qeff, g_qeff);
    cudaGetSymbolAddress((void**)&sc,   g_scores);
    cudaGetSymbolAddress((void**)&olat, g_olat);
    cudaGetSymbolAddress((void**)&o,    g_o);

    const double msc = 0.1*log(40.0) + 1.0;
    const float softmax_scale = (float)(pow((double)QD, -0.5)*msc*msc);

    // 1) rope tables
    rope_prep_kernel<<<(S_LEN*RHALF+127)/128, 128>>>(angles);

    // 2) q = x @ wq^T   (4096 x 3072, K=2048)
    launch_mma(true, 128, x, wq, q, NTOK, QOUT, DIM, DIM, DIM, QOUT,
               1, 1, 0,0, 0,0, 0,0, 1.f, false, false);

    // 3) kv = x @ wkv_a^T  (4096 x 576, K=2048): 512-wide + 64-wide
    launch_mma(true, 128, x, wkv_a, kv, NTOK, 512, DIM, DIM, DIM, KVOUT,
               1, 1, 0,0, 0,0, 0,0, 1.f, false, false);
    launch_mma(true, 64, x, wkv_a + (size_t)512*DIM, kv + 512, NTOK, 64, DIM, DIM, DIM, KVOUT,
               1, 1, 0,0, 0,0, 0,0, 1.f, false, false);

    // 4) keff = rmsnorm(kv_c)*w | rope(k_pe)
    prep_keff_kernel<<<NTOK, 128>>>(kvw);

    // 5) qeff[...,512:576] = rope(q_pe)
    prep_qpe_kernel<<<dim3(NTOK, NH), 32>>>();

    // 6) qeff[...,0:512] = q_nope @ wkv_b_nope   (per (b,h): 2048x512, K=128)
    launch_mma(false, 128, q, wkv_b, qeff, S_LEN, KVR, NOPE, QOUT, KVR, DEFF,
               BATCH*NH, NH,
               (ll)QD, (ll)S_LEN*QOUT,
               (ll)(NOPE+VDIM)*KVR, 0,
               (ll)S_LEN*DEFF, (ll)NH*S_LEN*DEFF,
               1.f, false, false);

    // 7) scores = scale * qeff @ keff^T  (per (b,h): 2048x2048, K=576), causal skip
    launch_mma(true, 128, qeff, keff, sc, S_LEN, S_LEN, DEFF, DEFF, DEFF, S_LEN,
               BATCH*NH, NH,
               (ll)S_LEN*DEFF, (ll)NH*S_LEN*DEFF,
               0, (ll)S_LEN*DEFF,
               (ll)S_LEN*S_LEN, (ll)NH*S_LEN*S_LEN,
               softmax_scale, true, false);

    // 8) causal softmax in place
    softmax_kernel<<<dim3(S_LEN, BATCH*NH), 128>>>(sc);

    // 9) olat = probs @ c  (per (b,h): 2048x512, K causally capped)
    launch_mma(false, 128, sc, keff, olat, S_LEN, KVR, S_LEN, S_LEN, DEFF, KVR,
               BATCH*NH, NH,
               (ll)S_LEN*S_LEN, (ll)NH*S_LEN*S_LEN,
               0, (ll)S_LEN*DEFF,
               (ll)S_LEN*KVR, (ll)NH*S_LEN*KVR,
               1.f, false, true);

    // 10) o[:, h*128:(h+1)*128] = olat_h @ wkv_b_v^T  (per (b,h): 2048x128, K=512)
    launch_mma(true, 128, olat, wkv_b + (size_t)NOPE*KVR, o, S_LEN, VDIM, KVR,
               KVR, KVR, NH*VDIM,
               BATCH*NH, NH,
               (ll)S_LEN*KVR, (ll)NH*S_LEN*KVR,
               (ll)(NOPE+VDIM)*KVR, 0,
               (ll)VDIM, (ll)S_LEN*NH*VDIM,
               1.f, false, false);

    // 11) out = o @ wo^T  (4096 x 2048, K=2048)
    launch_mma(true, 128, o, wo, out, NTOK, DIM, NH*VDIM, NH*VDIM, NH*VDIM, DIM,
               1, 1, 0,0, 0,0, 0,0, 1.f, false, false);
}